// round 15
// baseline (speedup 1.0000x reference)
#include <cuda_runtime.h>
#include <cuda_pipeline_primitives.h>

#define EMB 128
#define MAXB 1024
#define NW 8            // warps per pool block
#define ROWS_PER_CTA 256
#define GPB 8           // graphs per k_out block
#define PREPB 65        // 64 W1 blocks + 1 c block
#define STAGES 4        // cp.async pipeline depth
#define SROWS 16        // rows per stage (8 KB)

// Scratch (device globals; no allocation allowed).
// g_num/g_den are accumulated by k_main (atomics) and consumed+zeroed by
// k_out each call, so every graph replay starts from zero.
__device__ float g_num[MAXB * EMB];
__device__ float g_den[MAXB];
__device__ float g_W1[EMB * EMB];             // Wv @ Wm_top
__device__ float g_c[EMB];                    // bv @ Wm_top

// ---------------------------------------------------------------------------
// Kernel 1 (heterogeneous):
//  blk [0,64):  W1 rows (W1 = Wv @ Wm_top);  blk 64: g_c = bv @ Wm_top
//  blk [65, 65+ceil(N/256)): pooling over FIXED row range [pb*256,pb*256+256)
//    using the R10-proven cp.async 4-stage pipeline. Each warp accumulates
//    (sum e*x, sum e) for its current graph and atomically flushes on the
//    (warp-uniform) graph boundary. No segment scan needed.
//  softmax is shift-invariant and gates are O(5): exp without max is safe.
// ---------------------------------------------------------------------------
__global__ __launch_bounds__(256, 4) void k_main(
    const float* __restrict__ x, const int* __restrict__ bidx,
    const float* __restrict__ Wg, const float* __restrict__ bg,
    const float* __restrict__ Wv, const float* __restrict__ Wm,
    const float* __restrict__ bv, int N)
{
    __shared__ __align__(16) float smem_u[STAGES * SROWS * EMB];
    __shared__ int sbid[ROWS_PER_CTA];

    int blk = blockIdx.x;
    int tid = threadIdx.x;

    if (blk < 64) {
        float* av = smem_u;
        av[tid] = Wv[blk * (2 * EMB) + tid];
        __syncthreads();
        int j  = tid & (EMB - 1);
        int ih = tid >> 7;
        float acc = 0.f;
        #pragma unroll 16
        for (int k = 0; k < EMB; k++)
            acc += av[ih * EMB + k] * __ldg(Wm + k * EMB + j);
        g_W1[(blk * 2 + ih) * EMB + j] = acc;
        return;
    }
    if (blk == 64) {
        float* sb = smem_u;
        if (tid < EMB) sb[tid] = bv[tid];
        __syncthreads();
        if (tid < EMB) {
            float acc = 0.f;
            #pragma unroll 16
            for (int k = 0; k < EMB; k++)
                acc += sb[k] * __ldg(Wm + k * EMB + tid);
            g_c[tid] = acc;
        }
        return;
    }

    int pb = blk - PREPB;
    int r0 = pb * ROWS_PER_CTA;
    int cnt = N - r0;
    if (cnt > ROWS_PER_CTA) cnt = ROWS_PER_CTA;
    if (cnt <= 0) return;
    int qe    = r0 + cnt;
    int lastr = qe - 1;
    int nst   = (cnt + SROWS - 1) / SROWS;

    int lane = tid & 31;
    int w    = tid >> 5;

    // per-CTA graph ids (coalesced 1 KB; visible after first pipeline sync)
    sbid[tid] = __ldg(bidx + min(r0 + tid, N - 1));

    float4 wg  = ((const float4*)Wg)[lane];
    float  bg0 = __ldg(bg);

    float4 acc = make_float4(0.f, 0.f, 0.f, 0.f);
    float den = 0.f;
    int cg = -1;                                    // current graph of this warp

    float4* sx = (float4*)smem_u;                   // [STAGES][SROWS][32]
    const float4* xg = (const float4*)x;

    // prologue: fill the pipeline
    #pragma unroll
    for (int st = 0; st < STAGES; st++) {
        if (st < nst) {
            int buf = st & (STAGES - 1);
            #pragma unroll
            for (int k = 0; k < 2; k++) {
                int flat = tid + k * 256;
                int row  = flat >> 5, col = flat & 31;
                int r = min(r0 + st * SROWS + row, lastr);
                __pipeline_memcpy_async(&sx[buf * SROWS * 32 + flat],
                                        xg + (size_t)r * 32 + col, 16);
            }
        }
        __pipeline_commit();
    }

    for (int it = 0; it < nst; it++) {
        __pipeline_wait_prior(STAGES - 1);
        __syncthreads();

        int buf = it & (STAGES - 1);
        const float4* sb = sx + buf * SROWS * 32;
        int lr0 = it * SROWS + 2 * w;

        float4 v0 = sb[(2 * w) * 32 + lane];
        float4 v1 = sb[(2 * w + 1) * 32 + lane];
        float p0 = v0.x * wg.x + v0.y * wg.y + v0.z * wg.z + v0.w * wg.w;
        float p1 = v1.x * wg.x + v1.y * wg.y + v1.z * wg.z + v1.w * wg.w;
        #pragma unroll
        for (int off = 16; off; off >>= 1) {
            p0 += __shfl_xor_sync(0xffffffffu, p0, off);
            p1 += __shfl_xor_sync(0xffffffffu, p1, off);
        }

        if (r0 + lr0 < qe) {                          // warp-uniform
            int g = sbid[lr0];
            if (g != cg) {                            // warp-uniform, rare
                if (cg >= 0) {
                    atomicAdd(&g_num[cg * EMB + 4 * lane + 0], acc.x);
                    atomicAdd(&g_num[cg * EMB + 4 * lane + 1], acc.y);
                    atomicAdd(&g_num[cg * EMB + 4 * lane + 2], acc.z);
                    atomicAdd(&g_num[cg * EMB + 4 * lane + 3], acc.w);
                    if (lane == 0) atomicAdd(&g_den[cg], den);
                    acc = make_float4(0.f, 0.f, 0.f, 0.f);
                    den = 0.f;
                }
                cg = g;
            }
            float e = __expf(p0 + bg0);
            acc.x += e * v0.x; acc.y += e * v0.y;
            acc.z += e * v0.z; acc.w += e * v0.w;
            den += e;
        }
        if (r0 + lr0 + 1 < qe) {                      // warp-uniform
            int g = sbid[lr0 + 1];
            if (g != cg) {
                if (cg >= 0) {
                    atomicAdd(&g_num[cg * EMB + 4 * lane + 0], acc.x);
                    atomicAdd(&g_num[cg * EMB + 4 * lane + 1], acc.y);
                    atomicAdd(&g_num[cg * EMB + 4 * lane + 2], acc.z);
                    atomicAdd(&g_num[cg * EMB + 4 * lane + 3], acc.w);
                    if (lane == 0) atomicAdd(&g_den[cg], den);
                    acc = make_float4(0.f, 0.f, 0.f, 0.f);
                    den = 0.f;
                }
                cg = g;
            }
            float e = __expf(p1 + bg0);
            acc.x += e * v1.x; acc.y += e * v1.y;
            acc.z += e * v1.z; acc.w += e * v1.w;
            den += e;
        }

        __syncthreads();                              // done reading this buffer

        int st = it + STAGES;
        if (st < nst) {
            int nbuf = st & (STAGES - 1);
            #pragma unroll
            for (int k = 0; k < 2; k++) {
                int flat = tid + k * 256;
                int row  = flat >> 5, col = flat & 31;
                int r = min(r0 + st * SROWS + row, lastr);
                __pipeline_memcpy_async(&sx[nbuf * SROWS * 32 + flat],
                                        xg + (size_t)r * 32 + col, 16);
            }
        }
        __pipeline_commit();
    }

    // final flush
    if (cg >= 0) {
        atomicAdd(&g_num[cg * EMB + 4 * lane + 0], acc.x);
        atomicAdd(&g_num[cg * EMB + 4 * lane + 1], acc.y);
        atomicAdd(&g_num[cg * EMB + 4 * lane + 2], acc.z);
        atomicAdd(&g_num[cg * EMB + 4 * lane + 3], acc.w);
        if (lane == 0) atomicAdd(&g_den[cg], den);
    }
}

// ---------------------------------------------------------------------------
// Kernel 2: out = gp + leaky_relu( [s, gp] @ [W1; Wm_bot] + flag*c + bm )
//   s = g_num / g_den (accumulated by k_main); accumulators zeroed here for
//   the next call. 512 threads; warp w owns k-chunk [16w,16w+16); weight
//   loads front-batched around the staging phase.
// ---------------------------------------------------------------------------
extern __shared__ float smem_ko[];

__global__ __launch_bounds__(512) void k_out(
    const float* __restrict__ gp, const float* __restrict__ Wm,
    const float* __restrict__ bm, float* __restrict__ out)
{
    float*  Ash = smem_ko;                       // [GPB][2*EMB]
    float*  Fsh = Ash + GPB * 2 * EMB;           // [GPB]
    float4* Hsh = (float4*)(Fsh + GPB);          // [16][GPB][32]

    int gbase = blockIdx.x * GPB;
    int tid = threadIdx.x;
    int w    = tid >> 5;
    int lane = tid & 31;
    int k0   = w * 16;
    const float* W = (k0 < EMB) ? (g_W1 + (size_t)k0 * EMB)
                                : (Wm + (size_t)EMB * EMB + (size_t)(k0 - EMB) * EMB);

    // batch 1 of weight loads — independent of staging, issued first
    float4 wv0[8];
    #pragma unroll
    for (int kk = 0; kk < 8; kk++)
        wv0[kk] = __ldg(((const float4*)(W + (size_t)kk * EMB)) + lane);

    for (int idx = tid; idx < GPB * EMB; idx += 512) {
        int g = idx >> 7, c = idx & 127;
        int bb = gbase + g;
        float n = g_num[(size_t)bb * EMB + c];
        g_num[(size_t)bb * EMB + c] = 0.f;       // reset for next replay
        float d = g_den[bb];
        Ash[g * 2 * EMB + c]       = (d > 0.f) ? (n / d) : 0.f;
        Ash[g * 2 * EMB + EMB + c] = __ldg(gp + (size_t)bb * EMB + c);
        if (c == 0) Fsh[g] = (d > 0.f) ? 1.f : 0.f;
    }
    __syncthreads();
    if (tid < GPB) g_den[gbase + tid] = 0.f;     // reset after all reads

    {
        // batch 2 of weight loads — issued before any FMA consumes batch 1
        float4 wv1[8];
        #pragma unroll
        for (int kk = 0; kk < 8; kk++)
            wv1[kk] = __ldg(((const float4*)(W + (size_t)(8 + kk) * EMB)) + lane);

        float4 a0 = {0,0,0,0}, a1 = {0,0,0,0}, a2 = {0,0,0,0}, a3 = {0,0,0,0};
        float4 a4 = {0,0,0,0}, a5 = {0,0,0,0}, a6 = {0,0,0,0}, a7 = {0,0,0,0};

        #pragma unroll
        for (int kk = 0; kk < 16; kk++) {
            float4 wv = (kk < 8) ? wv0[kk] : wv1[kk - 8];
            int k = k0 + kk;
            float s0 = Ash[0 * 2 * EMB + k];
            float s1 = Ash[1 * 2 * EMB + k];
            float s2 = Ash[2 * 2 * EMB + k];
            float s3 = Ash[3 * 2 * EMB + k];
            float s4 = Ash[4 * 2 * EMB + k];
            float s5 = Ash[5 * 2 * EMB + k];
            float s6 = Ash[6 * 2 * EMB + k];
            float s7 = Ash[7 * 2 * EMB + k];
            a0.x += s0*wv.x; a0.y += s0*wv.y; a0.z += s0*wv.z; a0.w += s0*wv.w;
            a1.x += s1*wv.x; a1.y += s1*wv.y; a1.z += s1*wv.z; a1.w += s1*wv.w;
            a2.x += s2*wv.x; a2.y += s2*wv.y; a2.z += s2*wv.z; a2.w += s2*wv.w;
            a3.x += s3*wv.x; a3.y += s3*wv.y; a3.z += s3*wv.z; a3.w += s3*wv.w;
            a4.x += s4*wv.x; a4.y += s4*wv.y; a4.z += s4*wv.z; a4.w += s4*wv.w;
            a5.x += s5*wv.x; a5.y += s5*wv.y; a5.z += s5*wv.z; a5.w += s5*wv.w;
            a6.x += s6*wv.x; a6.y += s6*wv.y; a6.z += s6*wv.z; a6.w += s6*wv.w;
            a7.x += s7*wv.x; a7.y += s7*wv.y; a7.z += s7*wv.z; a7.w += s7*wv.w;
        }
        Hsh[(w * GPB + 0) * 32 + lane] = a0;
        Hsh[(w * GPB + 1) * 32 + lane] = a1;
        Hsh[(w * GPB + 2) * 32 + lane] = a2;
        Hsh[(w * GPB + 3) * 32 + lane] = a3;
        Hsh[(w * GPB + 4) * 32 + lane] = a4;
        Hsh[(w * GPB + 5) * 32 + lane] = a5;
        Hsh[(w * GPB + 6) * 32 + lane] = a6;
        Hsh[(w * GPB + 7) * 32 + lane] = a7;
    }
    __syncthreads();

    if (tid < 256) {
        int g  = tid >> 5;
        int j4 = tid & 31;
        float4 h = {0,0,0,0};
        #pragma unroll
        for (int ww = 0; ww < 16; ww++) {
            float4 p = Hsh[(ww * GPB + g) * 32 + j4];
            h.x += p.x; h.y += p.y; h.z += p.z; h.w += p.w;
        }
        float4 c4 = ((const float4*)g_c)[j4];
        float4 b4 = __ldg(((const float4*)bm) + j4);
        float4 r4 = ((const float4*)(Ash + g * 2 * EMB + EMB))[j4];
        float fl = Fsh[g];

        float4 o; float hh;
        hh = h.x + fl * c4.x + b4.x; o.x = r4.x + (hh > 0.f ? hh : 0.01f * hh);
        hh = h.y + fl * c4.y + b4.y; o.y = r4.y + (hh > 0.f ? hh : 0.01f * hh);
        hh = h.z + fl * c4.z + b4.z; o.z = r4.z + (hh > 0.f ? hh : 0.01f * hh);
        hh = h.w + fl * c4.w + b4.w; o.w = r4.w + (hh > 0.f ? hh : 0.01f * hh);

        ((float4*)(out + (size_t)(gbase + g) * EMB))[j4] = o;
    }
}

extern "C" void kernel_launch(void* const* d_in, const int* in_sizes, int n_in,
                              void* d_out, int out_size)
{
    const float* x    = (const float*)d_in[0];
    const float* gp   = (const float*)d_in[1];
    const int*   bidx = (const int*)  d_in[2];
    const float* Wg   = (const float*)d_in[3];
    const float* bg   = (const float*)d_in[4];
    const float* Wv   = (const float*)d_in[5];
    const float* bv   = (const float*)d_in[6];
    const float* Wm   = (const float*)d_in[7];
    const float* bm   = (const float*)d_in[8];
    float* out = (float*)d_out;

    int N = in_sizes[0] / EMB;
    int B = in_sizes[1] / EMB;

    const int ko_smem = (GPB * 2 * EMB + GPB) * (int)sizeof(float)
                      + 16 * GPB * 32 * (int)sizeof(float4);   // ~73.8 KB
    static bool attr_done = false;
    if (!attr_done) {
        cudaFuncSetAttribute(k_out, cudaFuncAttributeMaxDynamicSharedMemorySize, ko_smem);
        attr_done = true;
    }

    int npool = (N + ROWS_PER_CTA - 1) / ROWS_PER_CTA;
    k_main<<<PREPB + npool, 256>>>(x, bidx, Wg, bg, Wv, Wm, bv, N);
    k_out<<<B / GPB, 512, ko_smem>>>(gp, Wm, bm, out);
}

// round 16
// speedup vs baseline: 1.0435x; 1.0435x over previous
#include <cuda_runtime.h>
#include <cuda_pipeline_primitives.h>

#define EMB 128
#define MAXB 1024
#define NW 8            // warps per pool block
#define SPLIT 2         // pool blocks per graph
#define EGPB 4          // graphs per epilogue block
#define PREPB 65        // 64 W1 blocks + 1 c block
#define STAGES 4        // cp.async pipeline depth
#define SROWS 16        // rows per stage (8 KB)

// Scratch (device globals; no allocation allowed)
__device__ float g_num[MAXB * SPLIT * EMB];   // partial exp-weighted sums
__device__ float g_den[MAXB * SPLIT];         // partial exp sums
__device__ float g_W1[EMB * EMB];             // Wv @ Wm_top
__device__ float g_c[EMB];                    // bv @ Wm_top
__device__ int   g_start[MAXB + 1];           // segment boundaries
__device__ int   g_ready[MAXB / EGPB];        // pool blocks done per epi group
__device__ int   g_prep_cnt;                  // prep blocks done
__device__ int   g_epi_done;                  // epilogue blocks done

// ---------------------------------------------------------------------------
// Kernel 0: segment boundary scan, 4 nodes per thread; 5th value via shfl.
// ---------------------------------------------------------------------------
__global__ __launch_bounds__(256) void k_scan(
    const int* __restrict__ bidx, int N, int B)
{
    int t = blockIdx.x * 256 + threadIdx.x;
    int base = t * 4;
    int lane = threadIdx.x & 31;

    int cnt = N - base;
    if (cnt > 4) cnt = 4;
    if (cnt < 0) cnt = 0;

    int v0 = 0, v1 = 0, v2 = 0, v3 = 0;
    if (cnt == 4) {
        int4 a = __ldg((const int4*)(bidx + base));
        v0 = a.x; v1 = a.y; v2 = a.z; v3 = a.w;
    } else if (cnt > 0) {
        v0 = __ldg(bidx + base);
        if (cnt > 1) v1 = __ldg(bidx + base + 1);
        if (cnt > 2) v2 = __ldg(bidx + base + 2);
    }

    int nxt = __shfl_down_sync(0xffffffffu, v0, 1);
    int v4;
    if (lane == 31 || cnt < 4)
        v4 = (base + 4 < N && cnt == 4) ? __ldg(bidx + base + 4) : B;
    else
        v4 = (base + 4 < N) ? nxt : B;

    if (cnt == 0) return;

    if (base == 0)
        for (int b = 0; b <= v0; b++) g_start[b] = 0;

    int v[5] = {v0, v1, v2, v3, v4};
    #pragma unroll
    for (int j = 0; j < 4; j++) {
        if (j < cnt) {
            int cur = v[j];
            int nx  = (j + 1 == cnt) ? v4 : v[j + 1];
            for (int b = cur + 1; b <= nx; b++) g_start[b] = base + j + 1;
        }
    }
}

// ---------------------------------------------------------------------------
// Kernel 1 (heterogeneous, single launch after scan):
//  blk [0,64):            W1 rows (W1 = Wv @ Wm_top)
//  blk 64:                g_c = bv @ Wm_top
//  blk [65, 65+npool):    pooling (R10-proven cp.async 4-stage pipeline)
//  blk [65+npool, +nepi): epilogue, gated on the 8 pool blocks of its 4
//                         graphs via per-group counters -> overlaps pool drain
//  softmax is shift-invariant and gates are O(5): exp without max is safe.
// ---------------------------------------------------------------------------
__global__ __launch_bounds__(256, 4) void k_main(
    const float* __restrict__ x,
    const float* __restrict__ Wg, const float* __restrict__ bg,
    const float* __restrict__ Wv, const float* __restrict__ Wm,
    const float* __restrict__ bv, const float* __restrict__ gp,
    const float* __restrict__ bm, float* __restrict__ out,
    int npool, int nepi)
{
    __shared__ __align__(16) float smem_u[STAGES * SROWS * EMB + NW * EMB + NW];

    int blk = blockIdx.x;
    int tid = threadIdx.x;

    if (blk < 64) {
        float* av = smem_u;
        av[tid] = Wv[blk * (2 * EMB) + tid];
        __syncthreads();
        int j  = tid & (EMB - 1);
        int ih = tid >> 7;
        float acc = 0.f;
        #pragma unroll 16
        for (int k = 0; k < EMB; k++)
            acc += av[ih * EMB + k] * __ldg(Wm + k * EMB + j);
        g_W1[(blk * 2 + ih) * EMB + j] = acc;
        __syncthreads();
        if (tid == 0) { __threadfence(); atomicAdd(&g_prep_cnt, 1); }
        return;
    }
    if (blk == 64) {
        float* sb = smem_u;
        if (tid < EMB) sb[tid] = bv[tid];
        __syncthreads();
        if (tid < EMB) {
            float acc = 0.f;
            #pragma unroll 16
            for (int k = 0; k < EMB; k++)
                acc += sb[k] * __ldg(Wm + k * EMB + tid);
            g_c[tid] = acc;
        }
        __syncthreads();
        if (tid == 0) { __threadfence(); atomicAdd(&g_prep_cnt, 1); }
        return;
    }

    if (blk < PREPB + npool) {
        // ------------------------- pool block -------------------------
        int pb = blk - PREPB;
        int b  = pb / SPLIT;
        int s  = pb - b * SPLIT;
        int s0   = g_start[b];
        int len0 = g_start[b + 1] - s0;
        int qa   = s0 + (len0 * s)       / SPLIT;
        int qe   = s0 + (len0 * (s + 1)) / SPLIT;
        int len  = qe - qa;

        int lane = tid & 31;
        int w    = tid >> 5;

        float4 wg  = ((const float4*)Wg)[lane];
        float  bg0 = __ldg(bg);

        float4 acc = make_float4(0.f, 0.f, 0.f, 0.f);
        float denom = 0.f;

        float4* sx = (float4*)smem_u;                   // [STAGES][SROWS][32]
        const float4* xg = (const float4*)x;
        int nst   = (len + SROWS - 1) / SROWS;
        int lastr = qe - 1;

        if (len > 0) {
            #pragma unroll
            for (int st = 0; st < STAGES; st++) {
                if (st < nst) {
                    int buf = st & (STAGES - 1);
                    #pragma unroll
                    for (int k = 0; k < 2; k++) {
                        int flat = tid + k * 256;
                        int row  = flat >> 5, col = flat & 31;
                        int r = min(qa + st * SROWS + row, lastr);
                        __pipeline_memcpy_async(&sx[buf * SROWS * 32 + flat],
                                                xg + (size_t)r * 32 + col, 16);
                    }
                }
                __pipeline_commit();
            }

            for (int it = 0; it < nst; it++) {
                __pipeline_wait_prior(STAGES - 1);
                __syncthreads();

                int buf = it & (STAGES - 1);
                const float4* sb = sx + buf * SROWS * 32;
                int r0 = qa + it * SROWS + 2 * w;

                float4 v0 = sb[(2 * w) * 32 + lane];
                float4 v1 = sb[(2 * w + 1) * 32 + lane];
                float p0 = v0.x * wg.x + v0.y * wg.y + v0.z * wg.z + v0.w * wg.w;
                float p1 = v1.x * wg.x + v1.y * wg.y + v1.z * wg.z + v1.w * wg.w;
                #pragma unroll
                for (int off = 16; off; off >>= 1) {
                    p0 += __shfl_xor_sync(0xffffffffu, p0, off);
                    p1 += __shfl_xor_sync(0xffffffffu, p1, off);
                }
                float e0 = (r0     < qe) ? __expf(p0 + bg0) : 0.f;
                float e1 = (r0 + 1 < qe) ? __expf(p1 + bg0) : 0.f;
                acc.x += e0 * v0.x + e1 * v1.x;
                acc.y += e0 * v0.y + e1 * v1.y;
                acc.z += e0 * v0.z + e1 * v1.z;
                acc.w += e0 * v0.w + e1 * v1.w;
                denom += e0 + e1;

                __syncthreads();

                int st = it + STAGES;
                if (st < nst) {
                    int nbuf = st & (STAGES - 1);
                    #pragma unroll
                    for (int k = 0; k < 2; k++) {
                        int flat = tid + k * 256;
                        int row  = flat >> 5, col = flat & 31;
                        int r = min(qa + st * SROWS + row, lastr);
                        __pipeline_memcpy_async(&sx[nbuf * SROWS * 32 + flat],
                                                xg + (size_t)r * 32 + col, 16);
                    }
                }
                __pipeline_commit();
            }
        }

        float* sm_acc = smem_u + STAGES * SROWS * EMB;    // [NW][EMB]
        float* sm_d   = sm_acc + NW * EMB;
        __syncthreads();
        ((float4*)(sm_acc + w * EMB))[lane] = acc;
        if (lane == 0) sm_d[w] = denom;
        __syncthreads();

        if (tid < EMB) {
            float sv = 0.f, d = 0.f;
            #pragma unroll
            for (int j = 0; j < NW; j++) {
                sv += sm_acc[j * EMB + tid];
                d  += sm_d[j];
            }
            g_num[(size_t)pb * EMB + tid] = sv;
            if (tid == 0) g_den[pb] = d;
        }
        __syncthreads();
        if (tid == 0) {
            __threadfence();
            atomicAdd(&g_ready[pb >> 3], 1);   // 8 pool blocks per epi group
        }
        return;
    }

    // ------------------------- epilogue block -------------------------
    // out = gp + leaky_relu( [s, gp] @ [W1; Wm_bot] + flag*c + bm )
    int m = blk - (PREPB + npool);
    int gbase = m * EGPB;

    if (tid == 0) {
        while (*(volatile int*)&g_prep_cnt < PREPB) __nanosleep(64);
        while (*(volatile int*)&g_ready[m] < SPLIT * EGPB) __nanosleep(64);
        __threadfence();
    }
    __syncthreads();

    float*  Ash = smem_u;                        // [EGPB][2*EMB]
    float*  Fsh = smem_u + EGPB * 2 * EMB;       // [EGPB] (padded to 8)
    float4* Hsh = (float4*)(smem_u + EGPB * 2 * EMB + 8);  // [8][EGPB][32]

    int w    = tid >> 5;
    int lane = tid & 31;
    int k0   = w * 32;
    const float* W = (k0 < EMB) ? (g_W1 + (size_t)k0 * EMB)
                                : (Wm + (size_t)EMB * EMB + (size_t)(k0 - EMB) * EMB);

    for (int idx = tid; idx < EGPB * EMB; idx += 256) {
        int g = idx >> 7, c = idx & 127;
        int bb = gbase + g;
        float n = g_num[(size_t)(bb * SPLIT + 0) * EMB + c]
                + g_num[(size_t)(bb * SPLIT + 1) * EMB + c];
        float d = g_den[bb * SPLIT] + g_den[bb * SPLIT + 1];
        Ash[g * 2 * EMB + c]       = (d > 0.f) ? (n / d) : 0.f;
        Ash[g * 2 * EMB + EMB + c] = __ldg(gp + (size_t)bb * EMB + c);
        if (c == 0) Fsh[g] = (d > 0.f) ? 1.f : 0.f;
    }
    __syncthreads();

    {
        float4 a0 = {0,0,0,0}, a1 = {0,0,0,0}, a2 = {0,0,0,0}, a3 = {0,0,0,0};
        #pragma unroll
        for (int bq = 0; bq < 4; bq++) {
            float4 wv[8];
            #pragma unroll
            for (int i = 0; i < 8; i++)
                wv[i] = __ldg(((const float4*)(W + (size_t)(bq * 8 + i) * EMB)) + lane);
            #pragma unroll
            for (int i = 0; i < 8; i++) {
                int k = k0 + bq * 8 + i;
                float s0 = Ash[0 * 2 * EMB + k];
                float s1 = Ash[1 * 2 * EMB + k];
                float s2 = Ash[2 * 2 * EMB + k];
                float s3 = Ash[3 * 2 * EMB + k];
                a0.x += s0*wv[i].x; a0.y += s0*wv[i].y; a0.z += s0*wv[i].z; a0.w += s0*wv[i].w;
                a1.x += s1*wv[i].x; a1.y += s1*wv[i].y; a1.z += s1*wv[i].z; a1.w += s1*wv[i].w;
                a2.x += s2*wv[i].x; a2.y += s2*wv[i].y; a2.z += s2*wv[i].z; a2.w += s2*wv[i].w;
                a3.x += s3*wv[i].x; a3.y += s3*wv[i].y; a3.z += s3*wv[i].z; a3.w += s3*wv[i].w;
            }
        }
        Hsh[(w * EGPB + 0) * 32 + lane] = a0;
        Hsh[(w * EGPB + 1) * 32 + lane] = a1;
        Hsh[(w * EGPB + 2) * 32 + lane] = a2;
        Hsh[(w * EGPB + 3) * 32 + lane] = a3;
    }
    __syncthreads();

    if (tid < EGPB * 32) {
        int g  = tid >> 5;
        int j4 = tid & 31;
        float4 h = {0,0,0,0};
        #pragma unroll
        for (int ww = 0; ww < 8; ww++) {
            float4 p = Hsh[(ww * EGPB + g) * 32 + j4];
            h.x += p.x; h.y += p.y; h.z += p.z; h.w += p.w;
        }
        float4 c4 = ((const float4*)g_c)[j4];
        float4 b4 = __ldg(((const float4*)bm) + j4);
        float4 r4 = ((const float4*)(Ash + g * 2 * EMB + EMB))[j4];
        float fl = Fsh[g];

        float4 o; float hh;
        hh = h.x + fl * c4.x + b4.x; o.x = r4.x + (hh > 0.f ? hh : 0.01f * hh);
        hh = h.y + fl * c4.y + b4.y; o.y = r4.y + (hh > 0.f ? hh : 0.01f * hh);
        hh = h.z + fl * c4.z + b4.z; o.z = r4.z + (hh > 0.f ? hh : 0.01f * hh);
        hh = h.w + fl * c4.w + b4.w; o.w = r4.w + (hh > 0.f ? hh : 0.01f * hh);

        ((float4*)(out + (size_t)(gbase + g) * EMB))[j4] = o;
    }

    // reset counters for the next graph replay
    __syncthreads();
    if (tid == 0) {
        atomicExch(&g_ready[m], 0);
        int c = atomicAdd(&g_epi_done, 1);
        if (c == nepi - 1) {
            atomicExch(&g_prep_cnt, 0);
            atomicExch(&g_epi_done, 0);
        }
    }
}

extern "C" void kernel_launch(void* const* d_in, const int* in_sizes, int n_in,
                              void* d_out, int out_size)
{
    const float* x    = (const float*)d_in[0];
    const float* gp   = (const float*)d_in[1];
    const int*   bidx = (const int*)  d_in[2];
    const float* Wg   = (const float*)d_in[3];
    const float* bg   = (const float*)d_in[4];
    const float* Wv   = (const float*)d_in[5];
    const float* bv   = (const float*)d_in[6];
    const float* Wm   = (const float*)d_in[7];
    const float* bm   = (const float*)d_in[8];
    float* out = (float*)d_out;

    int N = in_sizes[0] / EMB;
    int B = in_sizes[1] / EMB;

    int npool = B * SPLIT;
    int nepi  = B / EGPB;

    int scan_grid = (N / 4 + 255) / 256;
    k_scan<<<scan_grid, 256>>>(bidx, N, B);
    k_main<<<PREPB + npool + nepi, 256>>>(x, Wg, bg, Wv, Wm, bv,
                                          gp, bm, out, npool, nepi);
}

// round 17
// speedup vs baseline: 1.1143x; 1.0679x over previous
#include <cuda_runtime.h>
#include <cuda_pipeline_primitives.h>

#define EMB 128
#define MAXB 1024
#define NW 8            // warps per pool block
#define SPLIT 2         // pool blocks per graph
#define GPB 8           // graphs per k_out block
#define PREPB 65        // 64 W1 blocks + 1 c block
#define STAGES 4        // cp.async pipeline depth
#define SROWS 16        // rows per stage (8 KB)

// Scratch (device globals; no allocation allowed)
__device__ float g_num[MAXB * SPLIT * EMB];   // partial exp-weighted sums
__device__ float g_den[MAXB * SPLIT];         // partial exp sums
__device__ float g_W1[EMB * EMB];             // Wv @ Wm_top
__device__ float g_c[EMB];                    // bv @ Wm_top
__device__ int   g_start[MAXB + 1];           // segment boundaries

// ---------------------------------------------------------------------------
// Kernel 0: segment boundary scan, 4 nodes per thread; 5th value via shfl.
// ---------------------------------------------------------------------------
__global__ __launch_bounds__(256) void k_scan(
    const int* __restrict__ bidx, int N, int B)
{
    int t = blockIdx.x * 256 + threadIdx.x;
    int base = t * 4;
    int lane = threadIdx.x & 31;

    int cnt = N - base;
    if (cnt > 4) cnt = 4;
    if (cnt < 0) cnt = 0;

    int v0 = 0, v1 = 0, v2 = 0, v3 = 0;
    if (cnt == 4) {
        int4 a = __ldg((const int4*)(bidx + base));
        v0 = a.x; v1 = a.y; v2 = a.z; v3 = a.w;
    } else if (cnt > 0) {
        v0 = __ldg(bidx + base);
        if (cnt > 1) v1 = __ldg(bidx + base + 1);
        if (cnt > 2) v2 = __ldg(bidx + base + 2);
    }

    int nxt = __shfl_down_sync(0xffffffffu, v0, 1);
    int v4;
    if (lane == 31 || cnt < 4)
        v4 = (base + 4 < N && cnt == 4) ? __ldg(bidx + base + 4) : B;
    else
        v4 = (base + 4 < N) ? nxt : B;

    if (cnt == 0) return;

    if (base == 0)
        for (int b = 0; b <= v0; b++) g_start[b] = 0;

    int v[5] = {v0, v1, v2, v3, v4};
    #pragma unroll
    for (int j = 0; j < 4; j++) {
        if (j < cnt) {
            int cur = v[j];
            int nx  = (j + 1 == cnt) ? v4 : v[j + 1];
            for (int b = cur + 1; b <= nx; b++) g_start[b] = base + j + 1;
        }
    }
}

// ---------------------------------------------------------------------------
// Kernel 1 (heterogeneous):
//  blk [0,64):  W1 rows (W1 = Wv @ Wm_top);  blk 64: g_c = bv @ Wm_top
//  blk [65, 65+B*SPLIT): exp-weighted pooling, cp.async 4-stage smem pipeline
//  (R10-proven structure). __launch_bounds__(256,5): 48 regs -> 5 CTAs/SM
//  (was reg-capped at 4; smem 37 KB allows 6). More in-flight stages per SM.
//  softmax is shift-invariant and gates are O(5): exp without max is safe.
// ---------------------------------------------------------------------------
__global__ __launch_bounds__(256, 5) void k_main(
    const float* __restrict__ x,
    const float* __restrict__ Wg, const float* __restrict__ bg,
    const float* __restrict__ Wv, const float* __restrict__ Wm,
    const float* __restrict__ bv)
{
    __shared__ __align__(16) float smem_u[STAGES * SROWS * EMB + NW * EMB + NW];

    int blk = blockIdx.x;
    int tid = threadIdx.x;

    if (blk < 64) {
        float* av = smem_u;
        av[tid] = Wv[blk * (2 * EMB) + tid];
        __syncthreads();
        int j  = tid & (EMB - 1);
        int ih = tid >> 7;
        float acc = 0.f;
        #pragma unroll 16
        for (int k = 0; k < EMB; k++)
            acc += av[ih * EMB + k] * __ldg(Wm + k * EMB + j);
        g_W1[(blk * 2 + ih) * EMB + j] = acc;
        return;
    }
    if (blk == 64) {
        float* sb = smem_u;
        if (tid < EMB) sb[tid] = bv[tid];
        __syncthreads();
        if (tid < EMB) {
            float acc = 0.f;
            #pragma unroll 16
            for (int k = 0; k < EMB; k++)
                acc += sb[k] * __ldg(Wm + k * EMB + tid);
            g_c[tid] = acc;
        }
        return;
    }

    int pb = blk - PREPB;
    int b  = pb / SPLIT;
    int s  = pb - b * SPLIT;
    int s0   = g_start[b];
    int len0 = g_start[b + 1] - s0;
    int qa   = s0 + (len0 * s)       / SPLIT;
    int qe   = s0 + (len0 * (s + 1)) / SPLIT;
    int len  = qe - qa;

    int lane = tid & 31;
    int w    = tid >> 5;

    float4 wg  = ((const float4*)Wg)[lane];
    float  bg0 = __ldg(bg);

    float4 acc = make_float4(0.f, 0.f, 0.f, 0.f);
    float denom = 0.f;

    float4* sx = (float4*)smem_u;                   // [STAGES][SROWS][32]
    const float4* xg = (const float4*)x;
    int nst   = (len + SROWS - 1) / SROWS;
    int lastr = qe - 1;

    if (len > 0) {
        // prologue: fill the pipeline (empty commits past nst keep counts uniform)
        #pragma unroll
        for (int st = 0; st < STAGES; st++) {
            if (st < nst) {
                int buf = st & (STAGES - 1);
                #pragma unroll
                for (int k = 0; k < 2; k++) {
                    int flat = tid + k * 256;
                    int row  = flat >> 5, col = flat & 31;
                    int r = min(qa + st * SROWS + row, lastr);
                    __pipeline_memcpy_async(&sx[buf * SROWS * 32 + flat],
                                            xg + (size_t)r * 32 + col, 16);
                }
            }
            __pipeline_commit();
        }

        for (int it = 0; it < nst; it++) {
            __pipeline_wait_prior(STAGES - 1);
            __syncthreads();

            int buf = it & (STAGES - 1);
            const float4* sb = sx + buf * SROWS * 32;
            int r0 = qa + it * SROWS + 2 * w;

            float4 v0 = sb[(2 * w) * 32 + lane];
            float4 v1 = sb[(2 * w + 1) * 32 + lane];
            float p0 = v0.x * wg.x + v0.y * wg.y + v0.z * wg.z + v0.w * wg.w;
            float p1 = v1.x * wg.x + v1.y * wg.y + v1.z * wg.z + v1.w * wg.w;
            #pragma unroll
            for (int off = 16; off; off >>= 1) {
                p0 += __shfl_xor_sync(0xffffffffu, p0, off);
                p1 += __shfl_xor_sync(0xffffffffu, p1, off);
            }
            float e0 = (r0     < qe) ? __expf(p0 + bg0) : 0.f;
            float e1 = (r0 + 1 < qe) ? __expf(p1 + bg0) : 0.f;
            acc.x += e0 * v0.x + e1 * v1.x;
            acc.y += e0 * v0.y + e1 * v1.y;
            acc.z += e0 * v0.z + e1 * v1.z;
            acc.w += e0 * v0.w + e1 * v1.w;
            denom += e0 + e1;

            __syncthreads();                          // done reading this buffer

            int st = it + STAGES;
            if (st < nst) {
                int nbuf = st & (STAGES - 1);
                #pragma unroll
                for (int k = 0; k < 2; k++) {
                    int flat = tid + k * 256;
                    int row  = flat >> 5, col = flat & 31;
                    int r = min(qa + st * SROWS + row, lastr);
                    __pipeline_memcpy_async(&sx[nbuf * SROWS * 32 + flat],
                                            xg + (size_t)r * 32 + col, 16);
                }
            }
            __pipeline_commit();
        }
    }

    float* sm_acc = smem_u + STAGES * SROWS * EMB;    // [NW][EMB]
    float* sm_d   = sm_acc + NW * EMB;
    __syncthreads();
    ((float4*)(sm_acc + w * EMB))[lane] = acc;
    if (lane == 0) sm_d[w] = denom;
    __syncthreads();

    if (tid < EMB) {
        float sv = 0.f, d = 0.f;
        #pragma unroll
        for (int j = 0; j < NW; j++) {
            sv += sm_acc[j * EMB + tid];
            d  += sm_d[j];
        }
        g_num[(size_t)pb * EMB + tid] = sv;
        if (tid == 0) g_den[pb] = d;
    }
}

// ---------------------------------------------------------------------------
// Kernel 2: out = gp + leaky_relu( [s, gp] @ [W1; Wm_bot] + flag*c + bm )
// 512 threads; warp w owns k-chunk [16w,16w+16); weight loads front-batched.
// ---------------------------------------------------------------------------
extern __shared__ float smem_ko[];

__global__ __launch_bounds__(512) void k_out(
    const float* __restrict__ gp, const float* __restrict__ Wm,
    const float* __restrict__ bm, float* __restrict__ out)
{
    float*  Ash = smem_ko;                       // [GPB][2*EMB]
    float*  Fsh = Ash + GPB * 2 * EMB;           // [GPB]
    float4* Hsh = (float4*)(Fsh + GPB);          // [16][GPB][32]

    int gbase = blockIdx.x * GPB;
    int tid = threadIdx.x;
    int w    = tid >> 5;
    int lane = tid & 31;
    int k0   = w * 16;
    const float* W = (k0 < EMB) ? (g_W1 + (size_t)k0 * EMB)
                                : (Wm + (size_t)EMB * EMB + (size_t)(k0 - EMB) * EMB);

    // batch 1 of weight loads — independent of staging, issued first
    float4 wv0[8];
    #pragma unroll
    for (int kk = 0; kk < 8; kk++)
        wv0[kk] = __ldg(((const float4*)(W + (size_t)kk * EMB)) + lane);

    for (int idx = tid; idx < GPB * EMB; idx += 512) {
        int g = idx >> 7, c = idx & 127;
        int bb = gbase + g;
        float n = 0.f, d = 0.f;
        #pragma unroll
        for (int s = 0; s < SPLIT; s++) {
            n += __ldg(&g_num[(size_t)(bb * SPLIT + s) * EMB + c]);
            d += __ldg(&g_den[bb * SPLIT + s]);
        }
        Ash[g * 2 * EMB + c]       = (d > 0.f) ? (n / d) : 0.f;
        Ash[g * 2 * EMB + EMB + c] = __ldg(gp + (size_t)bb * EMB + c);
        if (c == 0) Fsh[g] = (d > 0.f) ? 1.f : 0.f;
    }
    __syncthreads();

    {
        // batch 2 of weight loads — issued before any FMA consumes batch 1
        float4 wv1[8];
        #pragma unroll
        for (int kk = 0; kk < 8; kk++)
            wv1[kk] = __ldg(((const float4*)(W + (size_t)(8 + kk) * EMB)) + lane);

        float4 a0 = {0,0,0,0}, a1 = {0,0,0,0}, a2 = {0,0,0,0}, a3 = {0,0,0,0};
        float4 a4 = {0,0,0,0}, a5 = {0,0,0,0}, a6 = {0,0,0,0}, a7 = {0,0,0,0};

        #pragma unroll
        for (int kk = 0; kk < 16; kk++) {
            float4 wv = (kk < 8) ? wv0[kk] : wv1[kk - 8];
            int k = k0 + kk;
            float s0 = Ash[0 * 2 * EMB + k];
            float s1 = Ash[1 * 2 * EMB + k];
            float s2 = Ash[2 * 2 * EMB + k];
            float s3 = Ash[3 * 2 * EMB + k];
            float s4 = Ash[4 * 2 * EMB + k];
            float s5 = Ash[5 * 2 * EMB + k];
            float s6 = Ash[6 * 2 * EMB + k];
            float s7 = Ash[7 * 2 * EMB + k];
            a0.x += s0*wv.x; a0.y += s0*wv.y; a0.z += s0*wv.z; a0.w += s0*wv.w;
            a1.x += s1*wv.x; a1.y += s1*wv.y; a1.z += s1*wv.z; a1.w += s1*wv.w;
            a2.x += s2*wv.x; a2.y += s2*wv.y; a2.z += s2*wv.z; a2.w += s2*wv.w;
            a3.x += s3*wv.x; a3.y += s3*wv.y; a3.z += s3*wv.z; a3.w += s3*wv.w;
            a4.x += s4*wv.x; a4.y += s4*wv.y; a4.z += s4*wv.z; a4.w += s4*wv.w;
            a5.x += s5*wv.x; a5.y += s5*wv.y; a5.z += s5*wv.z; a5.w += s5*wv.w;
            a6.x += s6*wv.x; a6.y += s6*wv.y; a6.z += s6*wv.z; a6.w += s6*wv.w;
            a7.x += s7*wv.x; a7.y += s7*wv.y; a7.z += s7*wv.z; a7.w += s7*wv.w;
        }
        Hsh[(w * GPB + 0) * 32 + lane] = a0;
        Hsh[(w * GPB + 1) * 32 + lane] = a1;
        Hsh[(w * GPB + 2) * 32 + lane] = a2;
        Hsh[(w * GPB + 3) * 32 + lane] = a3;
        Hsh[(w * GPB + 4) * 32 + lane] = a4;
        Hsh[(w * GPB + 5) * 32 + lane] = a5;
        Hsh[(w * GPB + 6) * 32 + lane] = a6;
        Hsh[(w * GPB + 7) * 32 + lane] = a7;
    }
    __syncthreads();

    if (tid < 256) {
        int g  = tid >> 5;
        int j4 = tid & 31;
        float4 h = {0,0,0,0};
        #pragma unroll
        for (int ww = 0; ww < 16; ww++) {
            float4 p = Hsh[(ww * GPB + g) * 32 + j4];
            h.x += p.x; h.y += p.y; h.z += p.z; h.w += p.w;
        }
        float4 c4 = ((const float4*)g_c)[j4];
        float4 b4 = __ldg(((const float4*)bm) + j4);
        float4 r4 = ((const float4*)(Ash + g * 2 * EMB + EMB))[j4];
        float fl = Fsh[g];

        float4 o; float hh;
        hh = h.x + fl * c4.x + b4.x; o.x = r4.x + (hh > 0.f ? hh : 0.01f * hh);
        hh = h.y + fl * c4.y + b4.y; o.y = r4.y + (hh > 0.f ? hh : 0.01f * hh);
        hh = h.z + fl * c4.z + b4.z; o.z = r4.z + (hh > 0.f ? hh : 0.01f * hh);
        hh = h.w + fl * c4.w + b4.w; o.w = r4.w + (hh > 0.f ? hh : 0.01f * hh);

        ((float4*)(out + (size_t)(gbase + g) * EMB))[j4] = o;
    }
}

extern "C" void kernel_launch(void* const* d_in, const int* in_sizes, int n_in,
                              void* d_out, int out_size)
{
    const float* x    = (const float*)d_in[0];
    const float* gp   = (const float*)d_in[1];
    const int*   bidx = (const int*)  d_in[2];
    const float* Wg   = (const float*)d_in[3];
    const float* bg   = (const float*)d_in[4];
    const float* Wv   = (const float*)d_in[5];
    const float* bv   = (const float*)d_in[6];
    const float* Wm   = (const float*)d_in[7];
    const float* bm   = (const float*)d_in[8];
    float* out = (float*)d_out;

    int N = in_sizes[0] / EMB;
    int B = in_sizes[1] / EMB;

    const int ko_smem = (GPB * 2 * EMB + GPB) * (int)sizeof(float)
                      + 16 * GPB * 32 * (int)sizeof(float4);   // ~73.8 KB
    static bool attr_done = false;
    if (!attr_done) {
        cudaFuncSetAttribute(k_out, cudaFuncAttributeMaxDynamicSharedMemorySize, ko_smem);
        attr_done = true;
    }

    int scan_grid = (N / 4 + 255) / 256;
    k_scan<<<scan_grid, 256>>>(bidx, N, B);
    k_main<<<PREPB + B * SPLIT, 256>>>(x, Wg, bg, Wv, Wm, bv);
    k_out<<<B / GPB, 512, ko_smem>>>(gp, Wm, bm, out);
}